// round 5
// baseline (speedup 1.0000x reference)
#include <cuda_runtime.h>
#include <cuda_bf16.h>
#include <cstdint>

// DotInteraction: x [16384, 64, 128] fp32 -> upper-tri gram [16384, 2016] fp32.
// mma.sync m16n8k16 bf16 + ldmatrix (tcgen05 unavailable: harness targets sm_103 w/o 'a').
// Precision: x = hi + lo (bf16); D = hh + hl + lh, fp32 accumulate (rel err ~4e-6).
// Persistent double-buffered pipeline: 444 CTAs x 128 thr, each loops over ~37 batches.
// Per iter: prefetch-LDG next batch (2 reg waves) overlapped with compute halves,
// convert+STS into the other buffer, one __syncthreads per iteration.

#define FF 64
#define NPAIR 2016
#define GRIDP 444

constexpr int ROWB = 272;            // 256B row + 16B pad: conflict-free ldmatrix
constexpr int MATB = 64 * ROWB;      // 17408 B per matrix
constexpr int BUFB = 2 * MATB;       // [H][L] per buffer = 34816 B
constexpr int SM_TOTAL = 2 * BUFB;   // double buffer = 69632 B (3 CTAs/SM)

__device__ __forceinline__ uint32_t smem_u32(const void* p) {
    uint32_t a;
    asm("{ .reg .u64 t; cvta.to.shared.u64 t, %1; cvt.u32.u64 %0, t; }" : "=r"(a) : "l"(p));
    return a;
}
__device__ __forceinline__ void ldsm_x4(uint32_t* r, uint32_t addr) {
    asm volatile("ldmatrix.sync.aligned.m8n8.x4.shared.b16 {%0,%1,%2,%3}, [%4];"
                 : "=r"(r[0]), "=r"(r[1]), "=r"(r[2]), "=r"(r[3]) : "r"(addr));
}
__device__ __forceinline__ void ldsm_x2(uint32_t* r, uint32_t addr) {
    asm volatile("ldmatrix.sync.aligned.m8n8.x2.shared.b16 {%0,%1}, [%2];"
                 : "=r"(r[0]), "=r"(r[1]) : "r"(addr));
}
__device__ __forceinline__ void mma_bf16(float* c, const uint32_t* a, const uint32_t* b) {
    asm volatile(
        "mma.sync.aligned.m16n8k16.row.col.f32.bf16.bf16.f32 "
        "{%0,%1,%2,%3}, {%4,%5,%6,%7}, {%8,%9}, {%0,%1,%2,%3};"
        : "+f"(c[0]), "+f"(c[1]), "+f"(c[2]), "+f"(c[3])
        : "r"(a[0]), "r"(a[1]), "r"(a[2]), "r"(a[3]), "r"(b[0]), "r"(b[1]));
}

__device__ __forceinline__ uint32_t aoff(int rt, int lid) {
    return (uint32_t)(rt * 16 + (lid & 15)) * ROWB + (uint32_t)(lid >> 4) * 16;
}
__device__ __forceinline__ uint32_t boff(int c0, int lid) {
    return (uint32_t)(c0 * 8 + (lid & 7)) * ROWB + (uint32_t)((lid >> 3) & 1) * 16;
}

// Compute k-steps [K0,K1) for NC col-tiles of one row-stripe.
template <int NC, int K0, int K1>
__device__ __forceinline__ void group_k(float (&acc)[NC][4], uint32_t aH, uint32_t aL,
                                        uint32_t bH, uint32_t bL) {
#pragma unroll
    for (int kk = K0; kk < K1; ++kk) {
        uint32_t ah[4], al[4];
        ldsm_x4(ah, aH + kk * 32);
        ldsm_x4(al, aL + kk * 32);
#pragma unroll
        for (int c = 0; c < NC; ++c) {
            uint32_t bh[2], bl[2];
            ldsm_x2(bh, bH + c * (8 * ROWB) + kk * 32);
            ldsm_x2(bl, bL + c * (8 * ROWB) + kk * 32);
            mma_bf16(acc[c], ah, bh);   // hh
            mma_bf16(acc[c], ah, bl);   // hl
            mma_bf16(acc[c], al, bh);   // lh
        }
    }
}

template <int NC>
__device__ __forceinline__ void store_group(const float (&acc)[NC][4], float* __restrict__ ob,
                                            int rt, int c0, int lid) {
    const int rbase = rt * 16 + (lid >> 2);
    const int cbase = 2 * (lid & 3);
#pragma unroll
    for (int c = 0; c < NC; ++c) {
        const int j0 = 8 * (c0 + c) + cbase;
#pragma unroll
        for (int half = 0; half < 2; ++half) {
            const int i = rbase + 8 * half;
            const int rowoff = i * (2 * FF - i - 1) / 2 - i - 1;  // out idx = rowoff + j
#pragma unroll
            for (int d = 0; d < 2; ++d) {
                const int j = j0 + d;
                if (j > i) ob[rowoff + j] = acc[c][2 * half + d];
            }
        }
    }
}

// Convert one 8-float4 wave to hi/lo bf16 and STS into buffer at smemN.
__device__ __forceinline__ void store_wave(const float4* p, char* smemN, int tid, int j0) {
#pragma unroll
    for (int j = 0; j < 8; ++j) {
        int idx = tid + (j0 + j) * 128;    // 0..2047
        int row = idx >> 5;
        int k4 = (idx & 31) * 4;
        float4 v = p[j];
        __nv_bfloat16 h0 = __float2bfloat16(v.x);
        __nv_bfloat16 h1 = __float2bfloat16(v.y);
        __nv_bfloat16 h2 = __float2bfloat16(v.z);
        __nv_bfloat16 h3 = __float2bfloat16(v.w);
        __nv_bfloat16 l0 = __float2bfloat16(v.x - __bfloat162float(h0));
        __nv_bfloat16 l1 = __float2bfloat16(v.y - __bfloat162float(h1));
        __nv_bfloat16 l2 = __float2bfloat16(v.z - __bfloat162float(h2));
        __nv_bfloat16 l3 = __float2bfloat16(v.w - __bfloat162float(h3));
        __nv_bfloat162 hp0 = __halves2bfloat162(h0, h1);
        __nv_bfloat162 hp1 = __halves2bfloat162(h2, h3);
        __nv_bfloat162 lp0 = __halves2bfloat162(l0, l1);
        __nv_bfloat162 lp1 = __halves2bfloat162(l2, l3);
        int off = row * ROWB + k4 * 2;
        *reinterpret_cast<uint2*>(smemN + off) =
            make_uint2(*reinterpret_cast<uint32_t*>(&hp0), *reinterpret_cast<uint32_t*>(&hp1));
        *reinterpret_cast<uint2*>(smemN + MATB + off) =
            make_uint2(*reinterpret_cast<uint32_t*>(&lp0), *reinterpret_cast<uint32_t*>(&lp1));
    }
}

// One pipelined iteration for one warp: compute batch in buf[cur] while prefetching
// the next batch from gmem and staging it (convert+STS) into buf[next].
template <int NC0, int RT0, int C00, int NC1, int RT1, int C01>
__device__ __forceinline__ void warp_iter(uint32_t hC, uint32_t lC, char* smemN,
                                          const float4* __restrict__ xn,
                                          float* __restrict__ ob, int tid, int lid) {
    float acc0[NC0][4];
    float acc1[NC1 ? NC1 : 1][4];
#pragma unroll
    for (int c = 0; c < NC0; ++c)
#pragma unroll
        for (int e = 0; e < 4; ++e) acc0[c][e] = 0.0f;
    if constexpr (NC1 > 0) {
#pragma unroll
        for (int c = 0; c < NC1; ++c)
#pragma unroll
            for (int e = 0; e < 4; ++e) acc1[c][e] = 0.0f;
    }

    const uint32_t a0H = hC + aoff(RT0, lid), a0L = lC + aoff(RT0, lid);
    const uint32_t b0H = hC + boff(C00, lid), b0L = lC + boff(C00, lid);
    const uint32_t a1H = hC + aoff(RT1, lid), a1L = lC + aoff(RT1, lid);
    const uint32_t b1H = hC + boff(C01, lid), b1L = lC + boff(C01, lid);

    float4 p[8];
    // prefetch wave 0 (rows 0..31 of next batch)
#pragma unroll
    for (int j = 0; j < 8; ++j) p[j] = xn[tid + j * 128];

    // compute k-steps 0..3 (hides LDG latency)
    group_k<NC0, 0, 4>(acc0, a0H, a0L, b0H, b0L);
    if constexpr (NC1 > 0) group_k<NC1, 0, 4>(acc1, a1H, a1L, b1H, b1L);

    store_wave(p, smemN, tid, 0);

    // prefetch wave 1 (rows 32..63)
#pragma unroll
    for (int j = 0; j < 8; ++j) p[j] = xn[tid + (8 + j) * 128];

    // compute k-steps 4..7
    group_k<NC0, 4, 8>(acc0, a0H, a0L, b0H, b0L);
    if constexpr (NC1 > 0) group_k<NC1, 4, 8>(acc1, a1H, a1L, b1H, b1L);

    store_wave(p, smemN, tid, 8);

    // epilogue
    store_group<NC0>(acc0, ob, RT0, C00, lid);
    if constexpr (NC1 > 0) store_group<NC1>(acc1, ob, RT1, C01, lid);
}

__global__ void __launch_bounds__(128) dotint_pipe_kernel(const float* __restrict__ x,
                                                          float* __restrict__ out,
                                                          int nbatch) {
    extern __shared__ char smem[];
    const uint32_t sbase = smem_u32(smem);
    const int tid = threadIdx.x;
    const int lid = tid & 31;
    const int wid = tid >> 5;

    // prologue: stage batch blockIdx.x into buffer 0
    {
        const float4* xg = reinterpret_cast<const float4*>(x) + (size_t)blockIdx.x * 2048;
        float4 p[8];
#pragma unroll
        for (int j = 0; j < 8; ++j) p[j] = xg[tid + j * 128];
        store_wave(p, smem, tid, 0);
#pragma unroll
        for (int j = 0; j < 8; ++j) p[j] = xg[tid + (8 + j) * 128];
        store_wave(p, smem, tid, 8);
    }

    int cur = 0;
    for (int b = blockIdx.x; b < nbatch; b += GRIDP) {
        int bn = b + GRIDP;
        if (bn >= nbatch) bn = b;   // tail: reload current (result unused)
        __syncthreads();            // buf[cur] staged; buf[next] free for writing

        const uint32_t hC = sbase + (uint32_t)cur * BUFB;
        const uint32_t lC = hC + MATB;
        char* smemN = smem + (cur ^ 1) * BUFB;
        const float4* xn = reinterpret_cast<const float4*>(x) + (size_t)bn * 2048;
        float* ob = out + (size_t)b * NPAIR;

        switch (wid) {
            case 0: warp_iter<5, 0, 0, 0, 0, 0>(hC, lC, smemN, xn, ob, tid, lid); break;
            case 1: warp_iter<3, 0, 5, 2, 1, 2>(hC, lC, smemN, xn, ob, tid, lid); break;
            case 2: warp_iter<4, 1, 4, 1, 2, 4>(hC, lC, smemN, xn, ob, tid, lid); break;
            default: warp_iter<3, 2, 5, 2, 3, 6>(hC, lC, smemN, xn, ob, tid, lid); break;
        }
        cur ^= 1;
    }
}

extern "C" void kernel_launch(void* const* d_in, const int* in_sizes, int n_in,
                              void* d_out, int out_size) {
    const float* x = (const float*)d_in[0];
    float* out = (float*)d_out;
    int nbatch = in_sizes[0] / (FF * 128);   // 16384
    int grid = nbatch < GRIDP ? nbatch : GRIDP;
    cudaFuncSetAttribute(dotint_pipe_kernel, cudaFuncAttributeMaxDynamicSharedMemorySize, SM_TOTAL);
    dotint_pipe_kernel<<<grid, 128, SM_TOTAL>>>(x, out, nbatch);
}

// round 6
// speedup vs baseline: 1.5644x; 1.5644x over previous
#include <cuda_runtime.h>
#include <cuda_bf16.h>
#include <cstdint>

// DotInteraction: x [16384, 64, 128] fp32 -> upper-tri gram [16384, 2016] fp32.
// mma.sync m16n8k16 bf16 + ldmatrix (tcgen05 unavailable: harness targets sm_103 w/o 'a').
// Precision: x = hi + lo (bf16); D = hh + hl + lh, fp32 accumulate (rel err ~4e-6).
// 1 batch/CTA, 128 threads, 6 CTAs/SM. Column-pair partition: warp w owns col-pair
// (2w,2w+1); one ldmatrix.x4 loads the n16-wide B fragment for both columns, reused
// across all row-stripes -> B smem traffic halved, ldsm instruction count -45%.
// Tiles (3,6),(3,7) shifted to warp 0 for register balance (4/4/6/6 tiles per warp).

#define FF 64
#define NPAIR 2016

constexpr int ROWB = 272;            // 256B row + 16B pad: conflict-free ldmatrix
constexpr int MATB = 64 * ROWB;      // 17408 B per matrix
constexpr int SM_L = MATB;           // [H][L]
constexpr int SM_TOTAL = 2 * MATB;   // 34816 B

__device__ __forceinline__ uint32_t smem_u32(const void* p) {
    uint32_t a;
    asm("{ .reg .u64 t; cvta.to.shared.u64 t, %1; cvt.u32.u64 %0, t; }" : "=r"(a) : "l"(p));
    return a;
}
__device__ __forceinline__ void ldsm_x4(uint32_t* r, uint32_t addr) {
    asm volatile("ldmatrix.sync.aligned.m8n8.x4.shared.b16 {%0,%1,%2,%3}, [%4];"
                 : "=r"(r[0]), "=r"(r[1]), "=r"(r[2]), "=r"(r[3]) : "r"(addr));
}
__device__ __forceinline__ void mma_bf16(float* c, const uint32_t* a, const uint32_t* b) {
    asm volatile(
        "mma.sync.aligned.m16n8k16.row.col.f32.bf16.bf16.f32 "
        "{%0,%1,%2,%3}, {%4,%5,%6,%7}, {%8,%9}, {%0,%1,%2,%3};"
        : "+f"(c[0]), "+f"(c[1]), "+f"(c[2]), "+f"(c[3])
        : "r"(a[0]), "r"(a[1]), "r"(a[2]), "r"(a[3]), "r"(b[0]), "r"(b[1]));
}

// A fragment lane address (m16k16 x4): lanes 0-15 rows, 16-31 same rows k-hi half.
__device__ __forceinline__ uint32_t aoff(int rt, int lid) {
    return (uint32_t)(rt * 16 + (lid & 15)) * ROWB + (uint32_t)(lid >> 4) * 16;
}
// B fragment lane address (n16k16 x4 for col-pair CP): regs {0,1}=col 2CP, {2,3}=col 2CP+1.
__device__ __forceinline__ uint32_t bpoff(int cp, int lid) {
    int n = cp * 16 + ((lid >> 4) << 3) + (lid & 7);
    return (uint32_t)n * ROWB + (uint32_t)((lid >> 3) & 1) * 16;
}

template <int NC>
__device__ __forceinline__ void store_group(const float (&acc)[NC][4], float* __restrict__ ob,
                                            int rt, int c0, int lid) {
    const int rbase = rt * 16 + (lid >> 2);
    const int cbase = 2 * (lid & 3);
#pragma unroll
    for (int c = 0; c < NC; ++c) {
        const int j0 = 8 * (c0 + c) + cbase;
#pragma unroll
        for (int half = 0; half < 2; ++half) {
            const int i = rbase + 8 * half;
            const int rowoff = i * (2 * FF - i - 1) / 2 - i - 1;  // out idx = rowoff + j
#pragma unroll
            for (int d = 0; d < 2; ++d) {
                const int j = j0 + d;
                if (j > i) ob[rowoff + j] = acc[c][2 * half + d];
            }
        }
    }
}

// Process col-pair CP against row-stripes RT0..RT0+NS-1 (one B x4 load serves all stripes).
template <int RT0, int NS, int CP>
__device__ __forceinline__ void run_cpgroup(uint32_t baseH, uint32_t baseL,
                                            float* __restrict__ ob, int lid) {
    const uint32_t bo = bpoff(CP, lid);
    const uint32_t ao = aoff(RT0, lid);

    float acc[NS][8];
#pragma unroll
    for (int s = 0; s < NS; ++s)
#pragma unroll
        for (int e = 0; e < 8; ++e) acc[s][e] = 0.0f;

#pragma unroll
    for (int kk = 0; kk < 8; ++kk) {
        uint32_t bh[4], bl[4];
        ldsm_x4(bh, baseH + bo + kk * 32);
        ldsm_x4(bl, baseL + bo + kk * 32);
#pragma unroll
        for (int s = 0; s < NS; ++s) {
            uint32_t ah[4], al[4];
            ldsm_x4(ah, baseH + ao + s * (16 * ROWB) + kk * 32);
            ldsm_x4(al, baseL + ao + s * (16 * ROWB) + kk * 32);
            // col 2CP
            mma_bf16(acc[s] + 0, ah, bh + 0);
            mma_bf16(acc[s] + 0, ah, bl + 0);
            mma_bf16(acc[s] + 0, al, bh + 0);
            // col 2CP+1
            mma_bf16(acc[s] + 4, ah, bh + 2);
            mma_bf16(acc[s] + 4, ah, bl + 2);
            mma_bf16(acc[s] + 4, al, bh + 2);
        }
    }

#pragma unroll
    for (int s = 0; s < NS; ++s) {
        float a2[2][4];
#pragma unroll
        for (int e = 0; e < 4; ++e) { a2[0][e] = acc[s][e]; a2[1][e] = acc[s][4 + e]; }
        store_group<2>(a2, ob, RT0 + s, 2 * CP, lid);
    }
}

__global__ void __launch_bounds__(128, 6) dotint_mma_kernel(const float* __restrict__ x,
                                                            float* __restrict__ out) {
    extern __shared__ char smem[];
    const uint32_t sbase = smem_u32(smem);
    const int tid = threadIdx.x;
    const int lid = tid & 31;
    const int wid = tid >> 5;

    // ---- load batch (2048 float4), split hi/lo bf16, store padded rows ----
    const float4* xg = reinterpret_cast<const float4*>(x) + (size_t)blockIdx.x * 2048;
#pragma unroll
    for (int it = 0; it < 16; ++it) {
        int idx = tid + it * 128;          // 0..2047
        int row = idx >> 5;                // 0..63
        int k4 = (idx & 31) * 4;           // element col
        float4 v = xg[idx];

        __nv_bfloat16 h0 = __float2bfloat16(v.x);
        __nv_bfloat16 h1 = __float2bfloat16(v.y);
        __nv_bfloat16 h2 = __float2bfloat16(v.z);
        __nv_bfloat16 h3 = __float2bfloat16(v.w);
        __nv_bfloat16 l0 = __float2bfloat16(v.x - __bfloat162float(h0));
        __nv_bfloat16 l1 = __float2bfloat16(v.y - __bfloat162float(h1));
        __nv_bfloat16 l2 = __float2bfloat16(v.z - __bfloat162float(h2));
        __nv_bfloat16 l3 = __float2bfloat16(v.w - __bfloat162float(h3));

        __nv_bfloat162 hp0 = __halves2bfloat162(h0, h1);
        __nv_bfloat162 hp1 = __halves2bfloat162(h2, h3);
        __nv_bfloat162 lp0 = __halves2bfloat162(l0, l1);
        __nv_bfloat162 lp1 = __halves2bfloat162(l2, l3);

        int off = row * ROWB + k4 * 2;
        *reinterpret_cast<uint2*>(smem + off) =
            make_uint2(*reinterpret_cast<uint32_t*>(&hp0), *reinterpret_cast<uint32_t*>(&hp1));
        *reinterpret_cast<uint2*>(smem + SM_L + off) =
            make_uint2(*reinterpret_cast<uint32_t*>(&lp0), *reinterpret_cast<uint32_t*>(&lp1));
    }
    __syncthreads();

    // ---- compute: warp w -> col-pair w; tiles (3,6),(3,7) moved to warp 0 ----
    float* ob = out + (size_t)blockIdx.x * NPAIR;
    const uint32_t baseH = sbase, baseL = sbase + SM_L;

    switch (wid) {
        case 0:
            run_cpgroup<0, 1, 0>(baseH, baseL, ob, lid);   // (0,0) (0,1)
            run_cpgroup<3, 1, 3>(baseH, baseL, ob, lid);   // (3,6) (3,7)
            break;
        case 1:
            run_cpgroup<0, 2, 1>(baseH, baseL, ob, lid);   // rt0-1 x cols 2,3
            break;
        case 2:
            run_cpgroup<0, 3, 2>(baseH, baseL, ob, lid);   // rt0-2 x cols 4,5
            break;
        default:
            run_cpgroup<0, 3, 3>(baseH, baseL, ob, lid);   // rt0-2 x cols 6,7
            break;
    }
}

extern "C" void kernel_launch(void* const* d_in, const int* in_sizes, int n_in,
                              void* d_out, int out_size) {
    const float* x = (const float*)d_in[0];
    float* out = (float*)d_out;
    int nbatch = in_sizes[0] / (FF * 128);   // 16384
    cudaFuncSetAttribute(dotint_mma_kernel, cudaFuncAttributeMaxDynamicSharedMemorySize, SM_TOTAL);
    dotint_mma_kernel<<<nbatch, 128, SM_TOTAL>>>(x, out);
}

// round 8
// speedup vs baseline: 1.6352x; 1.0453x over previous
#include <cuda_runtime.h>
#include <cuda_bf16.h>
#include <cstdint>

// DotInteraction: x [16384, 64, 128] fp32 -> upper-tri gram [16384, 2016] fp32.
// mma.sync m16n8k16 bf16 + ldmatrix (tcgen05 unavailable: harness targets sm_103 w/o 'a').
// Precision: x = hi + lo (bf16); D = hh + hl + lh, fp32 accumulate (rel err ~4e-6).
// R7: swizzled no-pad smem (32KB/CTA -> 7 CTAs/SM), launch_bounds(128,7) reg cap,
// packed bf16x2 converts, unpredicated stores on off-diagonal tiles.
// Swizzle: byte(r, kc16) = (kc>>3)<<13 | r<<7 | (((kc&7)^(r&7))<<4)  [SW128 blocked atoms]

#define FF 64
#define NPAIR 2016

constexpr int MATB = 64 * 128 * 2;   // 16384 B per bf16 matrix (64 rows x 128 cols), swizzled
constexpr int SM_TOTAL = 2 * MATB;   // [H][L] = 32768 B

__device__ __forceinline__ uint32_t smem_u32(const void* p) {
    uint32_t a;
    asm("{ .reg .u64 t; cvta.to.shared.u64 t, %1; cvt.u32.u64 %0, t; }" : "=r"(a) : "l"(p));
    return a;
}
__device__ __forceinline__ void ldsm_x4(uint32_t* r, uint32_t addr) {
    asm volatile("ldmatrix.sync.aligned.m8n8.x4.shared.b16 {%0,%1,%2,%3}, [%4];"
                 : "=r"(r[0]), "=r"(r[1]), "=r"(r[2]), "=r"(r[3]) : "r"(addr));
}
__device__ __forceinline__ void mma_bf16(float* c, const uint32_t* a, const uint32_t* b) {
    asm volatile(
        "mma.sync.aligned.m16n8k16.row.col.f32.bf16.bf16.f32 "
        "{%0,%1,%2,%3}, {%4,%5,%6,%7}, {%8,%9}, {%0,%1,%2,%3};"
        : "+f"(c[0]), "+f"(c[1]), "+f"(c[2]), "+f"(c[3])
        : "r"(a[0]), "r"(a[1]), "r"(a[2]), "r"(a[3]), "r"(b[0]), "r"(b[1]));
}
__device__ __forceinline__ uint32_t cvt_bf16x2(float hi, float lo) {
    uint32_t r;
    asm("cvt.rn.bf16x2.f32 %0, %1, %2;" : "=r"(r) : "f"(hi), "f"(lo));
    return r;
}

// Col-pair CP (cols 16CP..16CP+15) against row-stripes RT0..RT0+NS-1 (16 rows each).
// One B x4 ldmatrix per (kk, h/l) serves all NS stripes.
template <int RT0, int NS, int CP>
__device__ __forceinline__ void run_cpgroup(uint32_t sb, float* __restrict__ ob, int lid) {
    // A fragment lane mapping: r = RT0*16 + (lid&15), k-chunk kc = 2kk + (lid>>4)
    const int hA = lid >> 4;
    const int rA = RT0 * 16 + (lid & 15);
    const uint32_t mA4 = (uint32_t)(((rA & 7) ^ hA) << 4);
    const uint32_t abase = sb + (uint32_t)(rA << 7);
    // B pair fragment: n = CP*16 + (hA<<3) + (lid&7), kc = 2kk + ((lid>>3)&1)
    const int qB = (lid >> 3) & 1;
    const int nx = lid & 7;
    const int nB = CP * 16 + (hA << 3) + nx;
    const uint32_t mB4 = (uint32_t)((nx ^ qB) << 4);
    const uint32_t bbase = sb + (uint32_t)(nB << 7);

    float acc[NS][8];
#pragma unroll
    for (int s = 0; s < NS; ++s)
#pragma unroll
        for (int e = 0; e < 8; ++e) acc[s][e] = 0.0f;

#pragma unroll
    for (int kk = 0; kk < 8; ++kk) {
        const uint32_t koff = (uint32_t)((kk >> 2) << 13);
        const uint32_t cb = (uint32_t)(((2 * kk) & 7) << 4);
        const uint32_t bOff = bbase + koff + (cb ^ mB4);
        uint32_t bh[4], bl[4];
        ldsm_x4(bh, bOff);
        ldsm_x4(bl, bOff + MATB);
#pragma unroll
        for (int s = 0; s < NS; ++s) {
            const uint32_t aOff = abase + (uint32_t)(s * 2048) + koff + (cb ^ mA4);
            uint32_t ah[4], al[4];
            ldsm_x4(ah, aOff);
            ldsm_x4(al, aOff + MATB);
            // col-tile 2CP
            mma_bf16(acc[s] + 0, ah, bh + 0);
            mma_bf16(acc[s] + 0, ah, bl + 0);
            mma_bf16(acc[s] + 0, al, bh + 0);
            // col-tile 2CP+1
            mma_bf16(acc[s] + 4, ah, bh + 2);
            mma_bf16(acc[s] + 4, ah, bl + 2);
            mma_bf16(acc[s] + 4, al, bh + 2);
        }
    }

    // epilogue: thread t -> rows (16(RT0+s) + t/4, +8), cols 8(2CP+cc) + 2(t%4) + d
    const int rb0 = (lid >> 2);
    const int cb0 = 2 * (lid & 3);
#pragma unroll
    for (int s = 0; s < NS; ++s) {
        const bool diag = (RT0 + s == CP);   // folds per unrolled s
        const int ib = (RT0 + s) * 16 + rb0;
#pragma unroll
        for (int cc = 0; cc < 2; ++cc) {
            const int j0 = 8 * (2 * CP + cc) + cb0;
#pragma unroll
            for (int half = 0; half < 2; ++half) {
                const int i = ib + 8 * half;
                const int rowoff = i * (2 * FF - i - 1) / 2 - i - 1;  // out idx = rowoff + j
#pragma unroll
                for (int d = 0; d < 2; ++d) {
                    const int j = j0 + d;
                    if (!diag || j > i) ob[rowoff + j] = acc[s][4 * cc + 2 * half + d];
                }
            }
        }
    }
}

__global__ void __launch_bounds__(128, 7) dotint_mma_kernel(const float* __restrict__ x,
                                                            float* __restrict__ out) {
    extern __shared__ char smem[];
    const uint32_t sb = smem_u32(smem);
    const int tid = threadIdx.x;
    const int lid = tid & 31;
    const int wid = tid >> 5;

    // ---- load batch (2048 float4), split hi/lo bf16 (packed cvt), store swizzled ----
    const float4* xg = reinterpret_cast<const float4*>(x) + (size_t)blockIdx.x * 2048;
#pragma unroll
    for (int it = 0; it < 16; ++it) {
        int idx = tid + it * 128;          // 0..2047
        int r = idx >> 5;                  // row 0..63
        int kc = (idx & 31) >> 1;          // 16B chunk 0..15
        int sub = (idx & 1) << 3;          // byte offset within chunk
        float4 v = xg[idx];

        uint32_t hp0 = cvt_bf16x2(v.y, v.x);
        uint32_t hp1 = cvt_bf16x2(v.w, v.z);
        float h0 = __uint_as_float(hp0 << 16);
        float h1 = __uint_as_float(hp0 & 0xffff0000u);
        float h2 = __uint_as_float(hp1 << 16);
        float h3 = __uint_as_float(hp1 & 0xffff0000u);
        uint32_t lp0 = cvt_bf16x2(v.y - h1, v.x - h0);
        uint32_t lp1 = cvt_bf16x2(v.w - h3, v.z - h2);

        uint32_t off = ((uint32_t)(kc >> 3) << 13) + ((uint32_t)r << 7) +
                       ((uint32_t)(((kc & 7) ^ (r & 7)) << 4)) + (uint32_t)sub;
        *reinterpret_cast<uint2*>(smem + off) = make_uint2(hp0, hp1);
        *reinterpret_cast<uint2*>(smem + MATB + off) = make_uint2(lp0, lp1);
    }
    __syncthreads();

    // ---- compute: warp w -> col-pair w; (3,6),(3,7) moved to warp 0 for reg balance ----
    float* ob = out + (size_t)blockIdx.x * NPAIR;
    switch (wid) {
        case 0:
            run_cpgroup<0, 1, 0>(sb, ob, lid);   // (0,0) (0,1)  [diag]
            run_cpgroup<3, 1, 3>(sb, ob, lid);   // (3,6) (3,7)  [diag]
            break;
        case 1:
            run_cpgroup<0, 2, 1>(sb, ob, lid);   // rt0-1 x cols 2,3
            break;
        case 2:
            run_cpgroup<0, 3, 2>(sb, ob, lid);   // rt0-2 x cols 4,5
            break;
        default:
            run_cpgroup<0, 3, 3>(sb, ob, lid);   // rt0-2 x cols 6,7
            break;
    }
}

extern "C" void kernel_launch(void* const* d_in, const int* in_sizes, int n_in,
                              void* d_out, int out_size) {
    const float* x = (const float*)d_in[0];
    float* out = (float*)d_out;
    int nbatch = in_sizes[0] / (FF * 128);   // 16384
    cudaFuncSetAttribute(dotint_mma_kernel, cudaFuncAttributeMaxDynamicSharedMemorySize, SM_TOTAL);
    dotint_mma_kernel<<<nbatch, 128, SM_TOTAL>>>(x, out);
}